// round 3
// baseline (speedup 1.0000x reference)
#include <cuda_runtime.h>
#include <cuda_bf16.h>

#define NN 65536
#define KK 6
#define MM 688
#define MQ (MM / 4)      // 172 float4 per (n,k) row
#define MH (MQ / 2)      // 86: each thread handles mq and mq+86

__global__ __launch_bounds__(256, 6)
void mlp_msg_agg_kernel(
    const float4* __restrict__ msgs,   // [N, K, MQ] as float4
    const int*    __restrict__ counts, // [N]
    const float*  __restrict__ ts,     // [N]
    const float*  __restrict__ W1,     // [6,3] row-major
    const float*  __restrict__ b1,     // [3]
    const float*  __restrict__ W2,     // [3,2]
    const float*  __restrict__ b2,     // [2]
    const float*  __restrict__ W3,     // [2,1]
    const float*  __restrict__ b3,     // [1]
    float4*       __restrict__ out,    // [N, MQ] as float4
    float*        __restrict__ out_ts) // [N] or null
{
    const int idx = blockIdx.x * blockDim.x + threadIdx.x;

    // piggyback the timestamps passthrough on the first N threads
    if (out_ts != nullptr && idx < NN) {
        out_ts[idx] = __ldg(ts + idx);
    }

    if (idx >= NN * MH) return;

    const int n  = idx / MH;
    const int mq = idx - n * MH;      // 0..85; this thread also does mq+86

    int k0 = KK - __ldg(counts + n);  // first valid slot
    if (k0 < 0) k0 = 0;

    const float bb1_0 = __ldg(b1 + 0), bb1_1 = __ldg(b1 + 1), bb1_2 = __ldg(b1 + 2);

    // h1 accumulators: 2 float4s x 4 lanes x 3 hidden = 24 regs
    float h[8][3];
    #pragma unroll
    for (int l = 0; l < 8; l++) {
        h[l][0] = bb1_0; h[l][1] = bb1_1; h[l][2] = bb1_2;
    }

    const float4* base = msgs + (size_t)n * KK * MQ + mq;

    // Fully unrolled; invalid slots are predicated-off LDGs (no HBM traffic).
    // __ldcs: streaming (evict-first) — zero reuse on msgs.
    #pragma unroll
    for (int k = 0; k < KK; k++) {
        if (k >= k0) {
            const float4 va = __ldcs(base + k * MQ);
            const float4 vb = __ldcs(base + k * MQ + MH);
            const float a = __ldg(W1 + k * 3 + 0);
            const float b = __ldg(W1 + k * 3 + 1);
            const float c = __ldg(W1 + k * 3 + 2);
            const float xa[4] = {va.x, va.y, va.z, va.w};
            const float xb[4] = {vb.x, vb.y, vb.z, vb.w};
            #pragma unroll
            for (int l = 0; l < 4; l++) {
                h[l][0]   = fmaf(xa[l], a, h[l][0]);
                h[l][1]   = fmaf(xa[l], b, h[l][1]);
                h[l][2]   = fmaf(xa[l], c, h[l][2]);
                h[l+4][0] = fmaf(xb[l], a, h[l+4][0]);
                h[l+4][1] = fmaf(xb[l], b, h[l+4][1]);
                h[l+4][2] = fmaf(xb[l], c, h[l+4][2]);
            }
        }
    }

    // Layers 2 & 3 (weights loaded late to shorten live ranges)
    const float w2_00 = __ldg(W2 + 0), w2_01 = __ldg(W2 + 1);
    const float w2_10 = __ldg(W2 + 2), w2_11 = __ldg(W2 + 3);
    const float w2_20 = __ldg(W2 + 4), w2_21 = __ldg(W2 + 5);
    const float bb2_0 = __ldg(b2 + 0), bb2_1 = __ldg(b2 + 1);
    const float w3_0  = __ldg(W3 + 0), w3_1  = __ldg(W3 + 1);
    const float bb3   = __ldg(b3 + 0);

    float res[8];
    #pragma unroll
    for (int l = 0; l < 8; l++) {
        const float a0 = fmaxf(h[l][0], 0.0f);
        const float a1 = fmaxf(h[l][1], 0.0f);
        const float a2 = fmaxf(h[l][2], 0.0f);
        float g0 = bb2_0, g1 = bb2_1;
        g0 = fmaf(a0, w2_00, g0); g1 = fmaf(a0, w2_01, g1);
        g0 = fmaf(a1, w2_10, g0); g1 = fmaf(a1, w2_11, g1);
        g0 = fmaf(a2, w2_20, g0); g1 = fmaf(a2, w2_21, g1);
        g0 = fmaxf(g0, 0.0f);
        g1 = fmaxf(g1, 0.0f);
        res[l] = fmaf(g0, w3_0, fmaf(g1, w3_1, bb3));
    }

    float4 oa, ob;
    oa.x = res[0]; oa.y = res[1]; oa.z = res[2]; oa.w = res[3];
    ob.x = res[4]; ob.y = res[5]; ob.z = res[6]; ob.w = res[7];
    float4* obase = out + (size_t)n * MQ + mq;
    __stcs(obase, oa);
    __stcs(obase + MH, ob);
}

extern "C" void kernel_launch(void* const* d_in, const int* in_sizes, int n_in,
                              void* d_out, int out_size)
{
    const float4* msgs   = (const float4*)d_in[0];
    const int*    counts = (const int*)  d_in[1];
    const float*  ts     = (const float*)d_in[2];
    const float*  W1     = (const float*)d_in[3];
    const float*  b1     = (const float*)d_in[4];
    const float*  W2     = (const float*)d_in[5];
    const float*  b2     = (const float*)d_in[6];
    const float*  W3     = (const float*)d_in[7];
    const float*  b3     = (const float*)d_in[8];

    float* out = (float*)d_out;
    const int write_ts = (out_size >= NN * MM + NN) ? 1 : 0;
    float* out_ts = write_ts ? (out + (size_t)NN * MM) : nullptr;

    const int total = NN * MH;                 // 5,636,096 threads
    const int threads = 256;
    const int blocks = (total + threads - 1) / threads;

    mlp_msg_agg_kernel<<<blocks, threads>>>(
        msgs, counts, ts, W1, b1, W2, b2, W3, b3,
        (float4*)out, out_ts);
}

// round 4
// speedup vs baseline: 1.1306x; 1.1306x over previous
#include <cuda_runtime.h>
#include <cuda_bf16.h>

#define NN 65536
#define KK 6
#define MM 688
#define MQ (MM / 4)      // 172 float4 per (n,k) row
#define MH (MQ / 2)      // 86: each thread handles mq and mq+86
#define TOTAL (NN * MH)  // 5,636,096 work items
#define NBLOCKS 740      // 148 SMs x 5 CTAs -- fully resident, persistent
#define NTHREADS 256

__global__ __launch_bounds__(NTHREADS, 5)
void mlp_msg_agg_kernel(
    const float4* __restrict__ msgs,   // [N, K, MQ] as float4
    const int*    __restrict__ counts, // [N]
    const float*  __restrict__ ts,     // [N]
    const float*  __restrict__ W1,     // [6,3] row-major
    const float*  __restrict__ b1,     // [3]
    const float*  __restrict__ W2,     // [3,2]
    const float*  __restrict__ b2,     // [2]
    const float*  __restrict__ W3,     // [2,1]
    const float*  __restrict__ b3,     // [1]
    float4*       __restrict__ out,    // [N, MQ] as float4
    float*        __restrict__ out_ts) // [N] or null
{
    const int tid0   = blockIdx.x * NTHREADS + threadIdx.x;
    const int stride = NBLOCKS * NTHREADS;   // 189,440

    // timestamps passthrough (first N threads; stride > N)
    if (out_ts != nullptr && tid0 < NN) {
        out_ts[tid0] = __ldg(ts + tid0);
    }

    const float bb1_0 = __ldg(b1 + 0), bb1_1 = __ldg(b1 + 1), bb1_2 = __ldg(b1 + 2);

    // Prefetch counts for the first iteration
    int idx = tid0;
    int c = 0;
    if (idx < TOTAL) c = __ldg(counts + idx / MH);

    while (idx < TOTAL) {
        const int n  = idx / MH;
        const int mq = idx - n * MH;

        int k0 = KK - c;
        if (k0 < 0) k0 = 0;

        const float4* base = msgs + (size_t)n * KK * MQ + mq;

        float h[8][3];
        #pragma unroll
        for (int l = 0; l < 8; l++) {
            h[l][0] = bb1_0; h[l][1] = bb1_1; h[l][2] = bb1_2;
        }

        // Front-batched predicated loads (invalid slots: no HBM traffic)
        #pragma unroll
        for (int k = 0; k < KK; k++) {
            if (k >= k0) {
                const float4 va = base[k * MQ];
                const float4 vb = base[k * MQ + MH];
                const float a = __ldg(W1 + k * 3 + 0);
                const float b = __ldg(W1 + k * 3 + 1);
                const float cc = __ldg(W1 + k * 3 + 2);
                const float xa[4] = {va.x, va.y, va.z, va.w};
                const float xb[4] = {vb.x, vb.y, vb.z, vb.w};
                #pragma unroll
                for (int l = 0; l < 4; l++) {
                    h[l][0]   = fmaf(xa[l], a,  h[l][0]);
                    h[l][1]   = fmaf(xa[l], b,  h[l][1]);
                    h[l][2]   = fmaf(xa[l], cc, h[l][2]);
                    h[l+4][0] = fmaf(xb[l], a,  h[l+4][0]);
                    h[l+4][1] = fmaf(xb[l], b,  h[l+4][1]);
                    h[l+4][2] = fmaf(xb[l], cc, h[l+4][2]);
                }
            }
        }

        // Prefetch next iteration's counts while FMAs drain
        const int idx2 = idx + stride;
        int c2 = 0;
        if (idx2 < TOTAL) c2 = __ldg(counts + idx2 / MH);

        const float w2_00 = __ldg(W2 + 0), w2_01 = __ldg(W2 + 1);
        const float w2_10 = __ldg(W2 + 2), w2_11 = __ldg(W2 + 3);
        const float w2_20 = __ldg(W2 + 4), w2_21 = __ldg(W2 + 5);
        const float bb2_0 = __ldg(b2 + 0), bb2_1 = __ldg(b2 + 1);
        const float w3_0  = __ldg(W3 + 0), w3_1  = __ldg(W3 + 1);
        const float bb3   = __ldg(b3 + 0);

        float res[8];
        #pragma unroll
        for (int l = 0; l < 8; l++) {
            const float a0 = fmaxf(h[l][0], 0.0f);
            const float a1 = fmaxf(h[l][1], 0.0f);
            const float a2 = fmaxf(h[l][2], 0.0f);
            float g0 = bb2_0, g1 = bb2_1;
            g0 = fmaf(a0, w2_00, g0); g1 = fmaf(a0, w2_01, g1);
            g0 = fmaf(a1, w2_10, g0); g1 = fmaf(a1, w2_11, g1);
            g0 = fmaf(a2, w2_20, g0); g1 = fmaf(a2, w2_21, g1);
            g0 = fmaxf(g0, 0.0f);
            g1 = fmaxf(g1, 0.0f);
            res[l] = fmaf(g0, w3_0, fmaf(g1, w3_1, bb3));
        }

        float4 oa, ob;
        oa.x = res[0]; oa.y = res[1]; oa.z = res[2]; oa.w = res[3];
        ob.x = res[4]; ob.y = res[5]; ob.z = res[6]; ob.w = res[7];
        float4* obase = out + (size_t)n * MQ + mq;
        obase[0]  = oa;
        obase[MH] = ob;

        idx = idx2;
        c   = c2;
    }
}

extern "C" void kernel_launch(void* const* d_in, const int* in_sizes, int n_in,
                              void* d_out, int out_size)
{
    const float4* msgs   = (const float4*)d_in[0];
    const int*    counts = (const int*)  d_in[1];
    const float*  ts     = (const float*)d_in[2];
    const float*  W1     = (const float*)d_in[3];
    const float*  b1     = (const float*)d_in[4];
    const float*  W2     = (const float*)d_in[5];
    const float*  b2     = (const float*)d_in[6];
    const float*  W3     = (const float*)d_in[7];
    const float*  b3     = (const float*)d_in[8];

    float* out = (float*)d_out;
    const int write_ts = (out_size >= NN * MM + NN) ? 1 : 0;
    float* out_ts = write_ts ? (out + (size_t)NN * MM) : nullptr;

    mlp_msg_agg_kernel<<<NBLOCKS, NTHREADS>>>(
        msgs, counts, ts, W1, b1, W2, b2, W3, b3,
        (float4*)out, out_ts);
}

// round 5
// speedup vs baseline: 1.1668x; 1.0320x over previous
#include <cuda_runtime.h>
#include <cstdint>

#define NN 65536
#define KK 6
#define MM 688
#define MQ 172               // float4 per row
#define ROW_BYTES 2752       // MM*4
#define NODE_BYTES 16512     // KK*ROW_BYTES
#define STAGES 8
#define NBLK 148
#define NTH 256
#define NCONS (NTH - 32)     // 224 consumer threads
#define MAXNPB 448           // ceil(65536/148)=443, padded

#define OFF_MBAR 0                         // 8 stages * (full,empty) * 8B = 128
#define OFF_CNT 128
#define OFF_BUF (OFF_CNT + MAXNPB * 4)     // 1920 (16B aligned)
#define SMEM_BYTES (OFF_BUF + STAGES * NODE_BYTES)  // 134016

extern __shared__ char smem[];

__device__ __forceinline__ uint32_t s2u(const void* p) {
    return (uint32_t)__cvta_generic_to_shared(p);
}

__device__ __forceinline__ void mbar_init(uint32_t mbar, uint32_t count) {
    asm volatile("mbarrier.init.shared.b64 [%0], %1;" :: "r"(mbar), "r"(count) : "memory");
}

__device__ __forceinline__ void mbar_expect_tx(uint32_t mbar, uint32_t bytes) {
    asm volatile("mbarrier.arrive.expect_tx.shared.b64 _, [%0], %1;"
                 :: "r"(mbar), "r"(bytes) : "memory");
}

__device__ __forceinline__ void mbar_arrive(uint32_t mbar) {
    asm volatile("mbarrier.arrive.shared.b64 _, [%0];" :: "r"(mbar) : "memory");
}

__device__ __forceinline__ void mbar_wait(uint32_t mbar, uint32_t parity) {
    asm volatile(
        "{\n\t"
        ".reg .pred P;\n\t"
        "WAIT_%=:\n\t"
        "mbarrier.try_wait.parity.acquire.cta.shared::cta.b64 P, [%0], %1, 0x989680;\n\t"
        "@!P bra WAIT_%=;\n\t"
        "}"
        :: "r"(mbar), "r"(parity) : "memory");
}

__device__ __forceinline__ void bulk_copy(uint32_t dst_smem, const void* src_gmem,
                                          uint32_t bytes, uint32_t mbar) {
    asm volatile(
        "cp.async.bulk.shared::cluster.global.mbarrier::complete_tx::bytes "
        "[%0], [%1], %2, [%3];"
        :: "r"(dst_smem), "l"(src_gmem), "r"(bytes), "r"(mbar) : "memory");
}

__global__ void __launch_bounds__(NTH, 1)
mlp_msg_agg_pipe(
    const char*  __restrict__ msgs,    // [N,K,M] f32 as bytes
    const int*   __restrict__ counts,  // [N]
    const float* __restrict__ ts,      // [N]
    const float* __restrict__ W1, const float* __restrict__ b1,
    const float* __restrict__ W2, const float* __restrict__ b2,
    const float* __restrict__ W3, const float* __restrict__ b3,
    float4*      __restrict__ out,     // [N, MQ]
    float*       __restrict__ out_ts)  // [N] or null
{
    const int tid = threadIdx.x;
    const int blk = blockIdx.x;
    const int start = (int)(((long long)blk * NN) / NBLK);
    const int end   = (int)(((long long)(blk + 1) * NN) / NBLK);
    const int nnode = end - start;

    int* s_cnt = (int*)(smem + OFF_CNT);
    const uint32_t mb = s2u(smem + OFF_MBAR);   // full(s)=mb+s*16, empty(s)=mb+s*16+8
    char* buf = smem + OFF_BUF;

    // Prologue: stage counts in smem, pass timestamps through
    for (int i = tid; i < nnode; i += NTH) {
        s_cnt[i] = counts[start + i];
        if (out_ts != nullptr) out_ts[start + i] = ts[start + i];
    }
    if (tid == 0) {
        #pragma unroll
        for (int s = 0; s < STAGES; s++) {
            mbar_init(mb + s * 16, 1);          // full: 1 expect_tx arrival
            mbar_init(mb + s * 16 + 8, NCONS);  // empty: all consumers arrive
        }
    }
    __syncthreads();

    if (tid < 32) {
        // ---------------- producer (single thread) ----------------
        if (tid == 0) {
            for (int i = 0; i < nnode; i++) {
                int c = s_cnt[i];
                c = (c < 0) ? 0 : ((c > KK) ? KK : c);
                const int s = i & (STAGES - 1);
                const uint32_t pp = ((i >> 3) & 1) ^ 1;   // producer parity (first 8 pass)
                mbar_wait(mb + s * 16 + 8, pp);           // wait stage empty
                const uint32_t bytes = (uint32_t)c * ROW_BYTES;
                mbar_expect_tx(mb + s * 16, bytes);
                if (bytes) {
                    const uint32_t dst =
                        s2u(buf + s * NODE_BYTES + (KK - c) * ROW_BYTES);
                    const char* src =
                        msgs + ((size_t)(start + i) * KK + (KK - c)) * ROW_BYTES;
                    bulk_copy(dst, src, bytes, mb + s * 16);
                }
            }
        }
        return;
    }

    // ---------------- consumers (224 threads, 172 active per node) ----------------
    const int ctid = tid - 32;

    float w1[KK * 3];
    #pragma unroll
    for (int i = 0; i < KK * 3; i++) w1[i] = __ldg(W1 + i);
    const float bb1_0 = __ldg(b1 + 0), bb1_1 = __ldg(b1 + 1), bb1_2 = __ldg(b1 + 2);
    const float w2_00 = __ldg(W2 + 0), w2_01 = __ldg(W2 + 1);
    const float w2_10 = __ldg(W2 + 2), w2_11 = __ldg(W2 + 3);
    const float w2_20 = __ldg(W2 + 4), w2_21 = __ldg(W2 + 5);
    const float bb2_0 = __ldg(b2 + 0), bb2_1 = __ldg(b2 + 1);
    const float w3_0  = __ldg(W3 + 0), w3_1  = __ldg(W3 + 1);
    const float bb3   = __ldg(b3 + 0);

    for (int i = 0; i < nnode; i++) {
        const int s = i & (STAGES - 1);
        const uint32_t p = (i >> 3) & 1;
        mbar_wait(mb + s * 16, p);              // wait stage full (acquire)

        if (ctid < MQ) {
            int c = s_cnt[i];
            int k0 = KK - c;
            if (k0 < 0) k0 = 0;
            if (k0 > KK) k0 = KK;

            const char* nb = buf + s * NODE_BYTES + ctid * 16;

            float h[4][3];
            #pragma unroll
            for (int l = 0; l < 4; l++) {
                h[l][0] = bb1_0; h[l][1] = bb1_1; h[l][2] = bb1_2;
            }

            #pragma unroll
            for (int k = 0; k < KK; k++) {
                if (k >= k0) {
                    const float4 v = *(const float4*)(nb + k * ROW_BYTES);
                    const float a = w1[k * 3 + 0];
                    const float bW = w1[k * 3 + 1];
                    const float cW = w1[k * 3 + 2];
                    const float x[4] = {v.x, v.y, v.z, v.w};
                    #pragma unroll
                    for (int l = 0; l < 4; l++) {
                        h[l][0] = fmaf(x[l], a,  h[l][0]);
                        h[l][1] = fmaf(x[l], bW, h[l][1]);
                        h[l][2] = fmaf(x[l], cW, h[l][2]);
                    }
                }
            }

            float res[4];
            #pragma unroll
            for (int l = 0; l < 4; l++) {
                const float a0 = fmaxf(h[l][0], 0.0f);
                const float a1 = fmaxf(h[l][1], 0.0f);
                const float a2 = fmaxf(h[l][2], 0.0f);
                float g0 = bb2_0, g1 = bb2_1;
                g0 = fmaf(a0, w2_00, g0); g1 = fmaf(a0, w2_01, g1);
                g0 = fmaf(a1, w2_10, g0); g1 = fmaf(a1, w2_11, g1);
                g0 = fmaf(a2, w2_20, g0); g1 = fmaf(a2, w2_21, g1);
                g0 = fmaxf(g0, 0.0f);
                g1 = fmaxf(g1, 0.0f);
                res[l] = fmaf(g0, w3_0, fmaf(g1, w3_1, bb3));
            }

            float4 o;
            o.x = res[0]; o.y = res[1]; o.z = res[2]; o.w = res[3];
            out[(size_t)(start + i) * MQ + ctid] = o;
        }

        mbar_arrive(mb + s * 16 + 8);           // release stage to producer
    }
}

extern "C" void kernel_launch(void* const* d_in, const int* in_sizes, int n_in,
                              void* d_out, int out_size)
{
    const char*  msgs   = (const char*) d_in[0];
    const int*   counts = (const int*)  d_in[1];
    const float* ts     = (const float*)d_in[2];
    const float* W1     = (const float*)d_in[3];
    const float* b1     = (const float*)d_in[4];
    const float* W2     = (const float*)d_in[5];
    const float* b2     = (const float*)d_in[6];
    const float* W3     = (const float*)d_in[7];
    const float* b3     = (const float*)d_in[8];

    float* out = (float*)d_out;
    const int write_ts = (out_size >= NN * MM + NN) ? 1 : 0;
    float* out_ts = write_ts ? (out + (size_t)NN * MM) : nullptr;

    cudaFuncSetAttribute(mlp_msg_agg_pipe,
                         cudaFuncAttributeMaxDynamicSharedMemorySize, SMEM_BYTES);

    mlp_msg_agg_pipe<<<NBLK, NTH, SMEM_BYTES>>>(
        msgs, counts, ts, W1, b1, W2, b2, W3, b3,
        (float4*)out, out_ts);
}

// round 7
// speedup vs baseline: 1.2533x; 1.0741x over previous
#include <cuda_runtime.h>
#include <cstdint>

#define NN 65536
#define KK 6
#define MM 688
#define MQ 172               // float4 per row
#define ROW_BYTES 2752       // MM*4
#define NODE_BYTES 16512     // KK*ROW_BYTES
#define STAGES 8
#define NBLK 148
#define NTH 512              // 1 producer warp + 2 consumer groups of 224
#define NCONS_G 224          // consumers per group (7 warps)
#define MAXNPB 448           // ceil(65536/148)=443, padded

#define OFF_MBAR 0                         // 8 stages * (full,empty) * 8B = 128
#define OFF_CNT 128
#define OFF_BUF (OFF_CNT + MAXNPB * 4)     // 1920 (16B aligned)
#define SMEM_BYTES (OFF_BUF + STAGES * NODE_BYTES)  // 134016

extern __shared__ char smem[];

__device__ __forceinline__ uint32_t s2u(const void* p) {
    return (uint32_t)__cvta_generic_to_shared(p);
}

__device__ __forceinline__ void mbar_init(uint32_t mbar, uint32_t count) {
    asm volatile("mbarrier.init.shared.b64 [%0], %1;" :: "r"(mbar), "r"(count) : "memory");
}

__device__ __forceinline__ void mbar_expect_tx(uint32_t mbar, uint32_t bytes) {
    asm volatile("mbarrier.arrive.expect_tx.shared.b64 _, [%0], %1;"
                 :: "r"(mbar), "r"(bytes) : "memory");
}

__device__ __forceinline__ void mbar_arrive(uint32_t mbar) {
    asm volatile("mbarrier.arrive.shared.b64 _, [%0];" :: "r"(mbar) : "memory");
}

__device__ __forceinline__ void mbar_wait(uint32_t mbar, uint32_t parity) {
    asm volatile(
        "{\n\t"
        ".reg .pred P;\n\t"
        "WAIT_%=:\n\t"
        "mbarrier.try_wait.parity.acquire.cta.shared::cta.b64 P, [%0], %1, 0x989680;\n\t"
        "@!P bra WAIT_%=;\n\t"
        "}"
        :: "r"(mbar), "r"(parity) : "memory");
}

__device__ __forceinline__ void bulk_copy(uint32_t dst_smem, const void* src_gmem,
                                          uint32_t bytes, uint32_t mbar) {
    asm volatile(
        "cp.async.bulk.shared::cluster.global.mbarrier::complete_tx::bytes "
        "[%0], [%1], %2, [%3];"
        :: "r"(dst_smem), "l"(src_gmem), "r"(bytes), "r"(mbar) : "memory");
}

__global__ void __launch_bounds__(NTH, 1)
mlp_msg_agg_pipe(
    const char*  __restrict__ msgs,    // [N,K,M] f32 as bytes
    const int*   __restrict__ counts,  // [N]
    const float* __restrict__ ts,      // [N]
    const float* __restrict__ W1, const float* __restrict__ b1,
    const float* __restrict__ W2, const float* __restrict__ b2,
    const float* __restrict__ W3, const float* __restrict__ b3,
    float4*      __restrict__ out,     // [N, MQ]
    float*       __restrict__ out_ts)  // [N] or null
{
    const int tid = threadIdx.x;
    const int blk = blockIdx.x;
    const int start = (int)(((long long)blk * NN) / NBLK);
    const int end   = (int)(((long long)(blk + 1) * NN) / NBLK);
    const int nnode = end - start;

    int* s_cnt = (int*)(smem + OFF_CNT);
    const uint32_t mb = s2u(smem + OFF_MBAR);   // full(s)=mb+s*16, empty(s)=mb+s*16+8
    char* buf = smem + OFF_BUF;

    // Prologue: stage counts in smem, pass timestamps through
    for (int i = tid; i < nnode; i += NTH) {
        s_cnt[i] = counts[start + i];
        if (out_ts != nullptr) out_ts[start + i] = ts[start + i];
    }
    if (tid == 0) {
        #pragma unroll
        for (int s = 0; s < STAGES; s++) {
            mbar_init(mb + s * 16, 1);            // full: 1 expect_tx arrival
            mbar_init(mb + s * 16 + 8, NCONS_G);  // empty: owning group arrives
        }
    }
    __syncthreads();

    if (tid < 32) {
        // ---------------- producer (single thread) ----------------
        if (tid == 0) {
            for (int i = 0; i < nnode; i++) {
                int c = s_cnt[i];
                c = (c < 0) ? 0 : ((c > KK) ? KK : c);
                const int s = i & (STAGES - 1);
                const uint32_t pp = ((i >> 3) & 1) ^ 1;   // first pass through each stage is free
                mbar_wait(mb + s * 16 + 8, pp);           // wait stage empty
                const uint32_t bytes = (uint32_t)c * ROW_BYTES;
                mbar_expect_tx(mb + s * 16, bytes);
                if (bytes) {
                    const uint32_t dst =
                        s2u(buf + s * NODE_BYTES + (KK - c) * ROW_BYTES);
                    const char* src =
                        msgs + ((size_t)(start + i) * KK + (KK - c)) * ROW_BYTES;
                    bulk_copy(dst, src, bytes, mb + s * 16);
                }
            }
        }
        return;
    }

    if (tid >= 32 + 2 * NCONS_G) return;       // idle tail threads

    // ---------------- consumers: 2 independent groups ----------------
    // Group 0 (tid 32..255):  even nodes -> even stages
    // Group 1 (tid 256..479): odd nodes  -> odd stages
    const int g    = (tid - 32) / NCONS_G;
    const int ctid = (tid - 32) - g * NCONS_G;  // 0..223; active if < MQ

    float w1[KK * 3];
    #pragma unroll
    for (int i = 0; i < KK * 3; i++) w1[i] = __ldg(W1 + i);
    const float bb1_0 = __ldg(b1 + 0), bb1_1 = __ldg(b1 + 1), bb1_2 = __ldg(b1 + 2);
    const float w2_00 = __ldg(W2 + 0), w2_01 = __ldg(W2 + 1);
    const float w2_10 = __ldg(W2 + 2), w2_11 = __ldg(W2 + 3);
    const float w2_20 = __ldg(W2 + 4), w2_21 = __ldg(W2 + 5);
    const float bb2_0 = __ldg(b2 + 0), bb2_1 = __ldg(b2 + 1);
    const float w3_0  = __ldg(W3 + 0), w3_1  = __ldg(W3 + 1);
    const float bb3   = __ldg(b3 + 0);

    for (int i = g; i < nnode; i += 2) {
        const int s = i & (STAGES - 1);
        const uint32_t p = (i >> 3) & 1;
        mbar_wait(mb + s * 16, p);              // wait stage full (acquire)

        if (ctid < MQ) {
            int c = s_cnt[i];
            int k0 = KK - c;
            if (k0 < 0) k0 = 0;
            if (k0 > KK) k0 = KK;

            const char* nb = buf + s * NODE_BYTES + ctid * 16;

            float h[4][3];
            #pragma unroll
            for (int l = 0; l < 4; l++) {
                h[l][0] = bb1_0; h[l][1] = bb1_1; h[l][2] = bb1_2;
            }

            #pragma unroll
            for (int k = 0; k < KK; k++) {
                if (k >= k0) {
                    const float4 v = *(const float4*)(nb + k * ROW_BYTES);
                    const float a  = w1[k * 3 + 0];
                    const float bW = w1[k * 3 + 1];
                    const float cW = w1[k * 3 + 2];
                    const float x[4] = {v.x, v.y, v.z, v.w};
                    #pragma unroll
                    for (int l = 0; l < 4; l++) {
                        h[l][0] = fmaf(x[l], a,  h[l][0]);
                        h[l][1] = fmaf(x[l], bW, h[l][1]);
                        h[l][2] = fmaf(x[l], cW, h[l][2]);
                    }
                }
            }

            float res[4];
            #pragma unroll
            for (int l = 0; l < 4; l++) {
                const float a0 = fmaxf(h[l][0], 0.0f);
                const float a1 = fmaxf(h[l][1], 0.0f);
                const float a2 = fmaxf(h[l][2], 0.0f);
                float g0 = bb2_0, g1 = bb2_1;
                g0 = fmaf(a0, w2_00, g0); g1 = fmaf(a0, w2_01, g1);
                g0 = fmaf(a1, w2_10, g0); g1 = fmaf(a1, w2_11, g1);
                g0 = fmaf(a2, w2_20, g0); g1 = fmaf(a2, w2_21, g1);
                g0 = fmaxf(g0, 0.0f);
                g1 = fmaxf(g1, 0.0f);
                res[l] = fmaf(g0, w3_0, fmaf(g1, w3_1, bb3));
            }

            float4 o;
            o.x = res[0]; o.y = res[1]; o.z = res[2]; o.w = res[3];
            out[(size_t)(start + i) * MQ + ctid] = o;
        }

        mbar_arrive(mb + s * 16 + 8);           // release stage to producer
    }
}

extern "C" void kernel_launch(void* const* d_in, const int* in_sizes, int n_in,
                              void* d_out, int out_size)
{
    const char*  msgs   = (const char*) d_in[0];
    const int*   counts = (const int*)  d_in[1];
    const float* ts     = (const float*)d_in[2];
    const float* W1     = (const float*)d_in[3];
    const float* b1     = (const float*)d_in[4];
    const float* W2     = (const float*)d_in[5];
    const float* b2     = (const float*)d_in[6];
    const float* W3     = (const float*)d_in[7];
    const float* b3     = (const float*)d_in[8];

    float* out = (float*)d_out;
    const int write_ts = (out_size >= NN * MM + NN) ? 1 : 0;
    float* out_ts = write_ts ? (out + (size_t)NN * MM) : nullptr;

    cudaFuncSetAttribute(mlp_msg_agg_pipe,
                         cudaFuncAttributeMaxDynamicSharedMemorySize, SMEM_BYTES);

    mlp_msg_agg_pipe<<<NBLK, NTH, SMEM_BYTES>>>(
        msgs, counts, ts, W1, b1, W2, b2, W3, b3,
        (float4*)out, out_ts);
}

// round 9
// speedup vs baseline: 1.2709x; 1.0140x over previous
#include <cuda_runtime.h>
#include <cstdint>

#define NN 65536
#define KK 6
#define MM 688
#define MQ 172               // float4 per row
#define ROW_BYTES 2752       // MM*4
#define NODE_BYTES 16512     // KK*ROW_BYTES
#define STAGES 9             // multiple of NGROUPS: stage -> fixed owning group
#define NBLK 148
#define NTH 768              // 1 producer warp + 3 consumer groups of 224
#define NGROUPS 3
#define NCONS_G 224          // consumers per group (7 warps)
#define MAXNPB 448           // ceil(65536/148)=443, padded

#define OFF_MBAR 0                         // 9 stages * (full,empty) * 8B = 144 -> pad 160
#define OFF_CNT 160
#define OFF_BUF (OFF_CNT + MAXNPB * 4)     // 1952 (16B aligned)
#define SMEM_BYTES (OFF_BUF + STAGES * NODE_BYTES)  // 150560

extern __shared__ char smem[];

__device__ __forceinline__ uint32_t s2u(const void* p) {
    return (uint32_t)__cvta_generic_to_shared(p);
}

__device__ __forceinline__ void mbar_init(uint32_t mbar, uint32_t count) {
    asm volatile("mbarrier.init.shared.b64 [%0], %1;" :: "r"(mbar), "r"(count) : "memory");
}

__device__ __forceinline__ void mbar_expect_tx(uint32_t mbar, uint32_t bytes) {
    asm volatile("mbarrier.arrive.expect_tx.shared.b64 _, [%0], %1;"
                 :: "r"(mbar), "r"(bytes) : "memory");
}

__device__ __forceinline__ void mbar_arrive(uint32_t mbar) {
    asm volatile("mbarrier.arrive.shared.b64 _, [%0];" :: "r"(mbar) : "memory");
}

__device__ __forceinline__ void mbar_wait(uint32_t mbar, uint32_t parity) {
    asm volatile(
        "{\n\t"
        ".reg .pred P;\n\t"
        "WAIT_%=:\n\t"
        "mbarrier.try_wait.parity.acquire.cta.shared::cta.b64 P, [%0], %1, 0x989680;\n\t"
        "@!P bra WAIT_%=;\n\t"
        "}"
        :: "r"(mbar), "r"(parity) : "memory");
}

__device__ __forceinline__ void bulk_copy(uint32_t dst_smem, const void* src_gmem,
                                          uint32_t bytes, uint32_t mbar) {
    asm volatile(
        "cp.async.bulk.shared::cluster.global.mbarrier::complete_tx::bytes "
        "[%0], [%1], %2, [%3];"
        :: "r"(dst_smem), "l"(src_gmem), "r"(bytes), "r"(mbar) : "memory");
}

__global__ void __launch_bounds__(NTH, 1)
mlp_msg_agg_pipe(
    const char*  __restrict__ msgs,    // [N,K,M] f32 as bytes
    const int*   __restrict__ counts,  // [N]
    const float* __restrict__ ts,      // [N]
    const float* __restrict__ W1, const float* __restrict__ b1,
    const float* __restrict__ W2, const float* __restrict__ b2,
    const float* __restrict__ W3, const float* __restrict__ b3,
    float4*      __restrict__ out,     // [N, MQ]
    float*       __restrict__ out_ts)  // [N] or null
{
    const int tid = threadIdx.x;
    const int blk = blockIdx.x;
    const int start = (int)(((long long)blk * NN) / NBLK);
    const int end   = (int)(((long long)(blk + 1) * NN) / NBLK);
    const int nnode = end - start;

    int* s_cnt = (int*)(smem + OFF_CNT);
    const uint32_t mb = s2u(smem + OFF_MBAR);   // full(s)=mb+s*16, empty(s)=mb+s*16+8
    char* buf = smem + OFF_BUF;

    // Prologue: stage counts in smem, pass timestamps through
    for (int i = tid; i < nnode; i += NTH) {
        s_cnt[i] = counts[start + i];
        if (out_ts != nullptr) out_ts[start + i] = ts[start + i];
    }
    if (tid == 0) {
        #pragma unroll
        for (int s = 0; s < STAGES; s++) {
            mbar_init(mb + s * 16, 1);            // full: 1 expect_tx arrival
            mbar_init(mb + s * 16 + 8, NCONS_G);  // empty: owning group arrives
        }
    }
    __syncthreads();

    if (tid < 32) {
        // ---------------- producer (single thread) ----------------
        if (tid == 0) {
            int s = 0;   // stage = i % STAGES (incremental)
            int j = 0;   // fill index = i / STAGES
            for (int i = 0; i < nnode; i++) {
                int c = s_cnt[i];
                c = (c < 0) ? 0 : ((c > KK) ? KK : c);
                const uint32_t pp = (j & 1) ^ 1;          // first pass through each stage is free
                mbar_wait(mb + s * 16 + 8, pp);           // wait stage empty
                const uint32_t bytes = (uint32_t)c * ROW_BYTES;
                mbar_expect_tx(mb + s * 16, bytes);
                if (bytes) {
                    const uint32_t dst =
                        s2u(buf + s * NODE_BYTES + (KK - c) * ROW_BYTES);
                    const char* src =
                        msgs + ((size_t)(start + i) * KK + (KK - c)) * ROW_BYTES;
                    bulk_copy(dst, src, bytes, mb + s * 16);
                }
                if (++s == STAGES) { s = 0; j++; }
            }
        }
        return;
    }

    if (tid >= 32 + NGROUPS * NCONS_G) return;   // idle tail threads

    // ---------------- consumers: 3 independent groups ----------------
    // Node i -> stage i % 9, group i % 3. Since 9 % 3 == 0, group g only
    // ever touches stages {g, g+3, g+6}: every stage has a FIXED owning
    // group, so successive fills of a stage are consumed sequentially by
    // the same threads -> producer is at most 1 fill ahead per stage ->
    // phase-parity protocol is safe (the R8 3-group/8-stage aliasing bug).
    const int g    = (tid - 32) / NCONS_G;
    const int ctid = (tid - 32) - g * NCONS_G;   // 0..223; active if < MQ

    float w1[KK * 3];
    #pragma unroll
    for (int i = 0; i < KK * 3; i++) w1[i] = __ldg(W1 + i);
    const float bb1_0 = __ldg(b1 + 0), bb1_1 = __ldg(b1 + 1), bb1_2 = __ldg(b1 + 2);
    const float w2_00 = __ldg(W2 + 0), w2_01 = __ldg(W2 + 1);
    const float w2_10 = __ldg(W2 + 2), w2_11 = __ldg(W2 + 3);
    const float w2_20 = __ldg(W2 + 4), w2_21 = __ldg(W2 + 5);
    const float bb2_0 = __ldg(b2 + 0), bb2_1 = __ldg(b2 + 1);
    const float w3_0  = __ldg(W3 + 0), w3_1  = __ldg(W3 + 1);
    const float bb3   = __ldg(b3 + 0);

    int s = g;   // stage of node i (cycles g, g+3, g+6)
    int j = 0;   // fill index = i / STAGES
    for (int i = g; i < nnode; i += NGROUPS) {
        mbar_wait(mb + s * 16, (uint32_t)(j & 1));   // wait stage full (acquire)

        if (ctid < MQ) {
            int c = s_cnt[i];
            int k0 = KK - c;
            if (k0 < 0) k0 = 0;
            if (k0 > KK) k0 = KK;

            const char* nb = buf + s * NODE_BYTES + ctid * 16;

            float h[4][3];
            #pragma unroll
            for (int l = 0; l < 4; l++) {
                h[l][0] = bb1_0; h[l][1] = bb1_1; h[l][2] = bb1_2;
            }

            #pragma unroll
            for (int k = 0; k < KK; k++) {
                if (k >= k0) {
                    const float4 v = *(const float4*)(nb + k * ROW_BYTES);
                    const float a  = w1[k * 3 + 0];
                    const float bW = w1[k * 3 + 1];
                    const float cW = w1[k * 3 + 2];
                    const float x[4] = {v.x, v.y, v.z, v.w};
                    #pragma unroll
                    for (int l = 0; l < 4; l++) {
                        h[l][0] = fmaf(x[l], a,  h[l][0]);
                        h[l][1] = fmaf(x[l], bW, h[l][1]);
                        h[l][2] = fmaf(x[l], cW, h[l][2]);
                    }
                }
            }

            float res[4];
            #pragma unroll
            for (int l = 0; l < 4; l++) {
                const float a0 = fmaxf(h[l][0], 0.0f);
                const float a1 = fmaxf(h[l][1], 0.0f);
                const float a2 = fmaxf(h[l][2], 0.0f);
                float g0 = bb2_0, g1 = bb2_1;
                g0 = fmaf(a0, w2_00, g0); g1 = fmaf(a0, w2_01, g1);
                g0 = fmaf(a1, w2_10, g0); g1 = fmaf(a1, w2_11, g1);
                g0 = fmaf(a2, w2_20, g0); g1 = fmaf(a2, w2_21, g1);
                g0 = fmaxf(g0, 0.0f);
                g1 = fmaxf(g1, 0.0f);
                res[l] = fmaf(g0, w3_0, fmaf(g1, w3_1, bb3));
            }

            float4 o;
            o.x = res[0]; o.y = res[1]; o.z = res[2]; o.w = res[3];
            out[(size_t)(start + i) * MQ + ctid] = o;
        }

        mbar_arrive(mb + s * 16 + 8);           // release stage to producer

        s += NGROUPS;
        if (s >= STAGES) { s -= STAGES; j++; }
    }
}

extern "C" void kernel_launch(void* const* d_in, const int* in_sizes, int n_in,
                              void* d_out, int out_size)
{
    const char*  msgs   = (const char*) d_in[0];
    const int*   counts = (const int*)  d_in[1];
    const float* ts     = (const float*)d_in[2];
    const float* W1     = (const float*)d_in[3];
    const float* b1     = (const float*)d_in[4];
    const float* W2     = (const float*)d_in[5];
    const float* b2     = (const float*)d_in[6];
    const float* W3     = (const float*)d_in[7];
    const float* b3     = (const float*)d_in[8];

    float* out = (float*)d_out;
    const int write_ts = (out_size >= NN * MM + NN) ? 1 : 0;
    float* out_ts = write_ts ? (out + (size_t)NN * MM) : nullptr;

    cudaFuncSetAttribute(mlp_msg_agg_pipe,
                         cudaFuncAttributeMaxDynamicSharedMemorySize, SMEM_BYTES);

    mlp_msg_agg_pipe<<<NBLK, NTH, SMEM_BYTES>>>(
        msgs, counts, ts, W1, b1, W2, b2, W3, b3,
        (float4*)out, out_ts);
}

// round 10
// speedup vs baseline: 1.2919x; 1.0166x over previous
#include <cuda_runtime.h>
#include <cstdint>

#define NN 65536
#define KK 6
#define MM 688
#define MQ 172               // float4 per row
#define ROW_BYTES 2752       // MM*4
#define NODE_BYTES 16512     // KK*ROW_BYTES
#define STAGES 12            // multiple of NGROUPS: stage -> fixed owning group
#define NBLK 148
#define NTH 800              // 1 producer warp + 4 consumer groups of 192
#define NGROUPS 4
#define NCONS_G 192          // consumers per group (6 warps, 172 active)
#define MAXNPB 448           // ceil(65536/148)=443, padded

#define OFF_MBAR 0                         // 12 stages * (full,empty) * 8B = 192
#define OFF_CNT 192
#define OFF_BUF (OFF_CNT + MAXNPB * 4)     // 1984 (16B aligned)
#define SMEM_BYTES (OFF_BUF + STAGES * NODE_BYTES)  // 200128

extern __shared__ char smem[];

__device__ __forceinline__ uint32_t s2u(const void* p) {
    return (uint32_t)__cvta_generic_to_shared(p);
}

__device__ __forceinline__ void mbar_init(uint32_t mbar, uint32_t count) {
    asm volatile("mbarrier.init.shared.b64 [%0], %1;" :: "r"(mbar), "r"(count) : "memory");
}

__device__ __forceinline__ void mbar_expect_tx(uint32_t mbar, uint32_t bytes) {
    asm volatile("mbarrier.arrive.expect_tx.shared.b64 _, [%0], %1;"
                 :: "r"(mbar), "r"(bytes) : "memory");
}

__device__ __forceinline__ void mbar_arrive(uint32_t mbar) {
    asm volatile("mbarrier.arrive.shared.b64 _, [%0];" :: "r"(mbar) : "memory");
}

__device__ __forceinline__ void mbar_wait(uint32_t mbar, uint32_t parity) {
    asm volatile(
        "{\n\t"
        ".reg .pred P;\n\t"
        "WAIT_%=:\n\t"
        "mbarrier.try_wait.parity.acquire.cta.shared::cta.b64 P, [%0], %1, 0x989680;\n\t"
        "@!P bra WAIT_%=;\n\t"
        "}"
        :: "r"(mbar), "r"(parity) : "memory");
}

__device__ __forceinline__ void bulk_copy(uint32_t dst_smem, const void* src_gmem,
                                          uint32_t bytes, uint32_t mbar) {
    asm volatile(
        "cp.async.bulk.shared::cluster.global.mbarrier::complete_tx::bytes "
        "[%0], [%1], %2, [%3];"
        :: "r"(dst_smem), "l"(src_gmem), "r"(bytes), "r"(mbar) : "memory");
}

__global__ void __launch_bounds__(NTH, 1)
mlp_msg_agg_pipe(
    const char*  __restrict__ msgs,    // [N,K,M] f32 as bytes
    const int*   __restrict__ counts,  // [N]
    const float* __restrict__ ts,      // [N]
    const float* __restrict__ W1, const float* __restrict__ b1,
    const float* __restrict__ W2, const float* __restrict__ b2,
    const float* __restrict__ W3, const float* __restrict__ b3,
    float4*      __restrict__ out,     // [N, MQ]
    float*       __restrict__ out_ts)  // [N] or null
{
    const int tid = threadIdx.x;
    const int blk = blockIdx.x;
    const int start = (int)(((long long)blk * NN) / NBLK);
    const int end   = (int)(((long long)(blk + 1) * NN) / NBLK);
    const int nnode = end - start;

    int* s_cnt = (int*)(smem + OFF_CNT);
    const uint32_t mb = s2u(smem + OFF_MBAR);   // full(s)=mb+s*16, empty(s)=mb+s*16+8
    char* buf = smem + OFF_BUF;

    // Prologue: stage counts in smem, pass timestamps through
    for (int i = tid; i < nnode; i += NTH) {
        s_cnt[i] = counts[start + i];
        if (out_ts != nullptr) out_ts[start + i] = ts[start + i];
    }
    if (tid == 0) {
        #pragma unroll
        for (int s = 0; s < STAGES; s++) {
            mbar_init(mb + s * 16, 1);            // full: 1 expect_tx arrival
            mbar_init(mb + s * 16 + 8, NCONS_G);  // empty: owning group arrives
        }
    }
    __syncthreads();

    if (tid < 32) {
        // ---------------- producer (single thread) ----------------
        if (tid == 0) {
            int s = 0;   // stage = i % STAGES (incremental)
            int j = 0;   // fill index = i / STAGES
            for (int i = 0; i < nnode; i++) {
                int c = s_cnt[i];
                c = (c < 0) ? 0 : ((c > KK) ? KK : c);
                const uint32_t pp = (j & 1) ^ 1;          // first pass through each stage is free
                mbar_wait(mb + s * 16 + 8, pp);           // wait stage empty
                const uint32_t bytes = (uint32_t)c * ROW_BYTES;
                mbar_expect_tx(mb + s * 16, bytes);
                if (bytes) {
                    const uint32_t dst =
                        s2u(buf + s * NODE_BYTES + (KK - c) * ROW_BYTES);
                    const char* src =
                        msgs + ((size_t)(start + i) * KK + (KK - c)) * ROW_BYTES;
                    bulk_copy(dst, src, bytes, mb + s * 16);
                }
                if (++s == STAGES) { s = 0; j++; }
            }
        }
        return;
    }

    if (tid >= 32 + NGROUPS * NCONS_G) return;   // idle tail threads

    // ---------------- consumers: 4 independent groups ----------------
    // Node i -> stage i % 12, group i % 4. Since 12 % 4 == 0, group g only
    // ever touches stages {g, g+4, g+8}: every stage has a FIXED owning
    // group, successive fills of a stage are consumed sequentially by the
    // same threads -> producer at most 1 fill ahead per stage -> the
    // phase-parity protocol is safe (no R8-style aliasing).
    const int g    = (tid - 32) / NCONS_G;
    const int ctid = (tid - 32) - g * NCONS_G;   // 0..191; active if < MQ

    float w1[KK * 3];
    #pragma unroll
    for (int i = 0; i < KK * 3; i++) w1[i] = __ldg(W1 + i);
    const float bb1_0 = __ldg(b1 + 0), bb1_1 = __ldg(b1 + 1), bb1_2 = __ldg(b1 + 2);
    const float w2_00 = __ldg(W2 + 0), w2_01 = __ldg(W2 + 1);
    const float w2_10 = __ldg(W2 + 2), w2_11 = __ldg(W2 + 3);
    const float w2_20 = __ldg(W2 + 4), w2_21 = __ldg(W2 + 5);
    const float bb2_0 = __ldg(b2 + 0), bb2_1 = __ldg(b2 + 1);
    const float w3_0  = __ldg(W3 + 0), w3_1  = __ldg(W3 + 1);
    const float bb3   = __ldg(b3 + 0);

    int s = g;   // stage of node i (cycles g, g+4, g+8)
    int j = 0;   // fill index = i / STAGES
    for (int i = g; i < nnode; i += NGROUPS) {
        mbar_wait(mb + s * 16, (uint32_t)(j & 1));   // wait stage full (acquire)

        if (ctid < MQ) {
            int c = s_cnt[i];
            int k0 = KK - c;
            if (k0 < 0) k0 = 0;
            if (k0 > KK) k0 = KK;

            const char* nb = buf + s * NODE_BYTES + ctid * 16;

            float h[4][3];
            #pragma unroll
            for (int l = 0; l < 4; l++) {
                h[l][0] = bb1_0; h[l][1] = bb1_1; h[l][2] = bb1_2;
            }

            #pragma unroll
            for (int k = 0; k < KK; k++) {
                if (k >= k0) {
                    const float4 v = *(const float4*)(nb + k * ROW_BYTES);
                    const float a  = w1[k * 3 + 0];
                    const float bW = w1[k * 3 + 1];
                    const float cW = w1[k * 3 + 2];
                    const float x[4] = {v.x, v.y, v.z, v.w};
                    #pragma unroll
                    for (int l = 0; l < 4; l++) {
                        h[l][0] = fmaf(x[l], a,  h[l][0]);
                        h[l][1] = fmaf(x[l], bW, h[l][1]);
                        h[l][2] = fmaf(x[l], cW, h[l][2]);
                    }
                }
            }

            float res[4];
            #pragma unroll
            for (int l = 0; l < 4; l++) {
                const float a0 = fmaxf(h[l][0], 0.0f);
                const float a1 = fmaxf(h[l][1], 0.0f);
                const float a2 = fmaxf(h[l][2], 0.0f);
                float g0 = bb2_0, g1 = bb2_1;
                g0 = fmaf(a0, w2_00, g0); g1 = fmaf(a0, w2_01, g1);
                g0 = fmaf(a1, w2_10, g0); g1 = fmaf(a1, w2_11, g1);
                g0 = fmaf(a2, w2_20, g0); g1 = fmaf(a2, w2_21, g1);
                g0 = fmaxf(g0, 0.0f);
                g1 = fmaxf(g1, 0.0f);
                res[l] = fmaf(g0, w3_0, fmaf(g1, w3_1, bb3));
            }

            float4 o;
            o.x = res[0]; o.y = res[1]; o.z = res[2]; o.w = res[3];
            out[(size_t)(start + i) * MQ + ctid] = o;
        }

        mbar_arrive(mb + s * 16 + 8);           // release stage to producer

        s += NGROUPS;
        if (s >= STAGES) { s -= STAGES; j++; }
    }
}

extern "C" void kernel_launch(void* const* d_in, const int* in_sizes, int n_in,
                              void* d_out, int out_size)
{
    const char*  msgs   = (const char*) d_in[0];
    const int*   counts = (const int*)  d_in[1];
    const float* ts     = (const float*)d_in[2];
    const float* W1     = (const float*)d_in[3];
    const float* b1     = (const float*)d_in[4];
    const float* W2     = (const float*)d_in[5];
    const float* b2     = (const float*)d_in[6];
    const float* W3     = (const float*)d_in[7];
    const float* b3     = (const float*)d_in[8];

    float* out = (float*)d_out;
    const int write_ts = (out_size >= NN * MM + NN) ? 1 : 0;
    float* out_ts = write_ts ? (out + (size_t)NN * MM) : nullptr;

    cudaFuncSetAttribute(mlp_msg_agg_pipe,
                         cudaFuncAttributeMaxDynamicSharedMemorySize, SMEM_BYTES);

    mlp_msg_agg_pipe<<<NBLK, NTH, SMEM_BYTES>>>(
        msgs, counts, ts, W1, b1, W2, b2, W3, b3,
        (float4*)out, out_ts);
}

// round 11
// speedup vs baseline: 1.3120x; 1.0155x over previous
#include <cuda_runtime.h>
#include <cstdint>

#define NN 65536
#define KK 6
#define MM 688
#define MQ 172               // float4 per row
#define ROW_BYTES 2752       // MM*4
#define NODE_BYTES 16512     // KK*ROW_BYTES
#define STAGES 12            // multiple of NGROUPS: stage -> fixed owning group
#define NBLK 148
#define NGROUPS 4
#define NCONS_G 192          // consumers per group (6 warps, 172 active)
#define NPROD_WARPS 4        // one producer warp per group
#define CONS_BASE (NPROD_WARPS * 32)          // 128
#define NTH (CONS_BASE + NGROUPS * NCONS_G)   // 896
#define MAXNPB 448           // ceil(65536/148)=443, padded

#define OFF_MBAR 0                         // 12 stages * (full,empty) * 8B = 192
#define OFF_CNT 192
#define OFF_BUF (OFF_CNT + MAXNPB * 4)     // 1984 (16B aligned)
#define SMEM_BYTES (OFF_BUF + STAGES * NODE_BYTES)  // 200128

extern __shared__ char smem[];

__device__ __forceinline__ uint32_t s2u(const void* p) {
    return (uint32_t)__cvta_generic_to_shared(p);
}

__device__ __forceinline__ void mbar_init(uint32_t mbar, uint32_t count) {
    asm volatile("mbarrier.init.shared.b64 [%0], %1;" :: "r"(mbar), "r"(count) : "memory");
}

__device__ __forceinline__ void mbar_expect_tx(uint32_t mbar, uint32_t bytes) {
    asm volatile("mbarrier.arrive.expect_tx.shared.b64 _, [%0], %1;"
                 :: "r"(mbar), "r"(bytes) : "memory");
}

__device__ __forceinline__ void mbar_arrive(uint32_t mbar) {
    asm volatile("mbarrier.arrive.shared.b64 _, [%0];" :: "r"(mbar) : "memory");
}

__device__ __forceinline__ void mbar_wait(uint32_t mbar, uint32_t parity) {
    asm volatile(
        "{\n\t"
        ".reg .pred P;\n\t"
        "WAIT_%=:\n\t"
        "mbarrier.try_wait.parity.acquire.cta.shared::cta.b64 P, [%0], %1, 0x989680;\n\t"
        "@!P bra WAIT_%=;\n\t"
        "}"
        :: "r"(mbar), "r"(parity) : "memory");
}

__device__ __forceinline__ void bulk_copy(uint32_t dst_smem, const void* src_gmem,
                                          uint32_t bytes, uint32_t mbar) {
    asm volatile(
        "cp.async.bulk.shared::cluster.global.mbarrier::complete_tx::bytes "
        "[%0], [%1], %2, [%3];"
        :: "r"(dst_smem), "l"(src_gmem), "r"(bytes), "r"(mbar) : "memory");
}

__global__ void __launch_bounds__(NTH, 1)
mlp_msg_agg_pipe(
    const char*  __restrict__ msgs,    // [N,K,M] f32 as bytes
    const int*   __restrict__ counts,  // [N]
    const float* __restrict__ ts,      // [N]
    const float* __restrict__ W1, const float* __restrict__ b1,
    const float* __restrict__ W2, const float* __restrict__ b2,
    const float* __restrict__ W3, const float* __restrict__ b3,
    float4*      __restrict__ out,     // [N, MQ]
    float*       __restrict__ out_ts)  // [N] or null
{
    const int tid = threadIdx.x;
    const int blk = blockIdx.x;
    const int start = (int)(((long long)blk * NN) / NBLK);
    const int end   = (int)(((long long)(blk + 1) * NN) / NBLK);
    const int nnode = end - start;

    int* s_cnt = (int*)(smem + OFF_CNT);
    const uint32_t mb = s2u(smem + OFF_MBAR);   // full(s)=mb+s*16, empty(s)=mb+s*16+8
    char* buf = smem + OFF_BUF;

    // Prologue: stage counts in smem, pass timestamps through
    for (int i = tid; i < nnode; i += NTH) {
        s_cnt[i] = counts[start + i];
        if (out_ts != nullptr) out_ts[start + i] = ts[start + i];
    }
    if (tid == 0) {
        #pragma unroll
        for (int s = 0; s < STAGES; s++) {
            mbar_init(mb + s * 16, 1);            // full: 1 expect_tx arrival
            mbar_init(mb + s * 16 + 8, NCONS_G);  // empty: owning group arrives
        }
    }
    __syncthreads();

    if (tid < CONS_BASE) {
        // ------------- producers: 4 warps, 1 active thread each -------------
        // Producer p (lane 0 of warp p) fills exactly group p's nodes
        // (i ≡ p mod 4) whose stages {p, p+4, p+8} it alone owns. Fills of
        // each stage stay strictly sequential by one thread -> parity safe.
        const int p = tid / 32;
        if ((tid & 31) == 0) {
            int s = p;   // stage of node i (cycles p, p+4, p+8)
            int j = 0;   // fill index = i / STAGES
            for (int i = p; i < nnode; i += NGROUPS) {
                int c = s_cnt[i];
                c = (c < 0) ? 0 : ((c > KK) ? KK : c);
                const uint32_t pp = (j & 1) ^ 1;          // first pass free
                mbar_wait(mb + s * 16 + 8, pp);           // wait stage empty
                const uint32_t bytes = (uint32_t)c * ROW_BYTES;
                mbar_expect_tx(mb + s * 16, bytes);
                if (bytes) {
                    const uint32_t dst =
                        s2u(buf + s * NODE_BYTES + (KK - c) * ROW_BYTES);
                    const char* src =
                        msgs + ((size_t)(start + i) * KK + (KK - c)) * ROW_BYTES;
                    bulk_copy(dst, src, bytes, mb + s * 16);
                }
                s += NGROUPS;
                if (s >= STAGES) { s -= STAGES; j++; }
            }
        }
        return;
    }

    // ---------------- consumers: 4 independent groups ----------------
    // Node i -> stage i % 12, group i % 4. 12 % 4 == 0 ⇒ every stage has a
    // fixed owning group; successive fills consumed sequentially by the same
    // threads ⇒ phase-parity protocol safe.
    const int g    = (tid - CONS_BASE) / NCONS_G;
    const int ctid = (tid - CONS_BASE) - g * NCONS_G;   // 0..191; active if < MQ

    float w1[KK * 3];
    #pragma unroll
    for (int i = 0; i < KK * 3; i++) w1[i] = __ldg(W1 + i);
    const float bb1_0 = __ldg(b1 + 0), bb1_1 = __ldg(b1 + 1), bb1_2 = __ldg(b1 + 2);
    const float w2_00 = __ldg(W2 + 0), w2_01 = __ldg(W2 + 1);
    const float w2_10 = __ldg(W2 + 2), w2_11 = __ldg(W2 + 3);
    const float w2_20 = __ldg(W2 + 4), w2_21 = __ldg(W2 + 5);
    const float bb2_0 = __ldg(b2 + 0), bb2_1 = __ldg(b2 + 1);
    const float w3_0  = __ldg(W3 + 0), w3_1  = __ldg(W3 + 1);
    const float bb3   = __ldg(b3 + 0);

    int s = g;   // stage of node i (cycles g, g+4, g+8)
    int j = 0;   // fill index = i / STAGES
    for (int i = g; i < nnode; i += NGROUPS) {
        mbar_wait(mb + s * 16, (uint32_t)(j & 1));   // wait stage full (acquire)

        if (ctid < MQ) {
            int c = s_cnt[i];
            int k0 = KK - c;
            if (k0 < 0) k0 = 0;
            if (k0 > KK) k0 = KK;

            const char* nb = buf + s * NODE_BYTES + ctid * 16;

            float h[4][3];
            #pragma unroll
            for (int l = 0; l < 4; l++) {
                h[l][0] = bb1_0; h[l][1] = bb1_1; h[l][2] = bb1_2;
            }

            #pragma unroll
            for (int k = 0; k < KK; k++) {
                if (k >= k0) {
                    const float4 v = *(const float4*)(nb + k * ROW_BYTES);
                    const float a  = w1[k * 3 + 0];
                    const float bW = w1[k * 3 + 1];
                    const float cW = w1[k * 3 + 2];
                    const float x[4] = {v.x, v.y, v.z, v.w};
                    #pragma unroll
                    for (int l = 0; l < 4; l++) {
                        h[l][0] = fmaf(x[l], a,  h[l][0]);
                        h[l][1] = fmaf(x[l], bW, h[l][1]);
                        h[l][2] = fmaf(x[l], cW, h[l][2]);
                    }
                }
            }

            float res[4];
            #pragma unroll
            for (int l = 0; l < 4; l++) {
                const float a0 = fmaxf(h[l][0], 0.0f);
                const float a1 = fmaxf(h[l][1], 0.0f);
                const float a2 = fmaxf(h[l][2], 0.0f);
                float g0 = bb2_0, g1 = bb2_1;
                g0 = fmaf(a0, w2_00, g0); g1 = fmaf(a0, w2_01, g1);
                g0 = fmaf(a1, w2_10, g0); g1 = fmaf(a1, w2_11, g1);
                g0 = fmaf(a2, w2_20, g0); g1 = fmaf(a2, w2_21, g1);
                g0 = fmaxf(g0, 0.0f);
                g1 = fmaxf(g1, 0.0f);
                res[l] = fmaf(g0, w3_0, fmaf(g1, w3_1, bb3));
            }

            float4 o;
            o.x = res[0]; o.y = res[1]; o.z = res[2]; o.w = res[3];
            out[(size_t)(start + i) * MQ + ctid] = o;
        }

        mbar_arrive(mb + s * 16 + 8);           // release stage to producer

        s += NGROUPS;
        if (s >= STAGES) { s -= STAGES; j++; }
    }
}

extern "C" void kernel_launch(void* const* d_in, const int* in_sizes, int n_in,
                              void* d_out, int out_size)
{
    const char*  msgs   = (const char*) d_in[0];
    const int*   counts = (const int*)  d_in[1];
    const float* ts     = (const float*)d_in[2];
    const float* W1     = (const float*)d_in[3];
    const float* b1     = (const float*)d_in[4];
    const float* W2     = (const float*)d_in[5];
    const float* b2     = (const float*)d_in[6];
    const float* W3     = (const float*)d_in[7];
    const float* b3     = (const float*)d_in[8];

    float* out = (float*)d_out;
    const int write_ts = (out_size >= NN * MM + NN) ? 1 : 0;
    float* out_ts = write_ts ? (out + (size_t)NN * MM) : nullptr;

    cudaFuncSetAttribute(mlp_msg_agg_pipe,
                         cudaFuncAttributeMaxDynamicSharedMemorySize, SMEM_BYTES);

    mlp_msg_agg_pipe<<<NBLK, NTH, SMEM_BYTES>>>(
        msgs, counts, ts, W1, b1, W2, b2, W3, b3,
        (float4*)out, out_ts);
}

// round 12
// speedup vs baseline: 1.3143x; 1.0018x over previous
#include <cuda_runtime.h>
#include <cstdint>

#define NN 65536
#define KK 6
#define MM 688
#define MQ 172               // float4 per row
#define ROW_BYTES 2752       // MM*4
#define NODE_BYTES 16512     // KK*ROW_BYTES
#define STAGES 6             // per-CTA; multiple of NGROUPS
#define NBLK 296             // 148 SMs x 2 CTAs (one wave)
#define NGROUPS 2
#define NCONS_G 192          // consumers per group (6 warps, 172 active)
#define NPROD_WARPS 2        // one producer warp per group
#define CONS_BASE (NPROD_WARPS * 32)          // 64
#define NTH (CONS_BASE + NGROUPS * NCONS_G)   // 448
#define MAXNPB 224           // ceil(65536/296)=222, padded

#define OFF_MBAR 0                         // 6 stages * (full,empty) * 8B = 96 -> pad 128
#define OFF_CNT 128
#define OFF_BUF (OFF_CNT + MAXNPB * 4)     // 1024 (16B aligned)
#define SMEM_BYTES (OFF_BUF + STAGES * NODE_BYTES)  // 100096 -> 2 CTAs/SM

extern __shared__ char smem[];

__device__ __forceinline__ uint32_t s2u(const void* p) {
    return (uint32_t)__cvta_generic_to_shared(p);
}

__device__ __forceinline__ void mbar_init(uint32_t mbar, uint32_t count) {
    asm volatile("mbarrier.init.shared.b64 [%0], %1;" :: "r"(mbar), "r"(count) : "memory");
}

__device__ __forceinline__ void mbar_expect_tx(uint32_t mbar, uint32_t bytes) {
    asm volatile("mbarrier.arrive.expect_tx.shared.b64 _, [%0], %1;"
                 :: "r"(mbar), "r"(bytes) : "memory");
}

__device__ __forceinline__ void mbar_arrive(uint32_t mbar) {
    asm volatile("mbarrier.arrive.shared.b64 _, [%0];" :: "r"(mbar) : "memory");
}

__device__ __forceinline__ void mbar_wait(uint32_t mbar, uint32_t parity) {
    asm volatile(
        "{\n\t"
        ".reg .pred P;\n\t"
        "WAIT_%=:\n\t"
        "mbarrier.try_wait.parity.acquire.cta.shared::cta.b64 P, [%0], %1, 0x989680;\n\t"
        "@!P bra WAIT_%=;\n\t"
        "}"
        :: "r"(mbar), "r"(parity) : "memory");
}

__device__ __forceinline__ void bulk_copy(uint32_t dst_smem, const void* src_gmem,
                                          uint32_t bytes, uint32_t mbar) {
    asm volatile(
        "cp.async.bulk.shared::cluster.global.mbarrier::complete_tx::bytes "
        "[%0], [%1], %2, [%3];"
        :: "r"(dst_smem), "l"(src_gmem), "r"(bytes), "r"(mbar) : "memory");
}

__global__ void __launch_bounds__(NTH, 2)
mlp_msg_agg_pipe(
    const char*  __restrict__ msgs,    // [N,K,M] f32 as bytes
    const int*   __restrict__ counts,  // [N]
    const float* __restrict__ ts,      // [N]
    const float* __restrict__ W1, const float* __restrict__ b1,
    const float* __restrict__ W2, const float* __restrict__ b2,
    const float* __restrict__ W3, const float* __restrict__ b3,
    float4*      __restrict__ out,     // [N, MQ]
    float*       __restrict__ out_ts)  // [N] or null
{
    const int tid = threadIdx.x;
    const int blk = blockIdx.x;
    const int start = (int)(((long long)blk * NN) / NBLK);
    const int end   = (int)(((long long)(blk + 1) * NN) / NBLK);
    const int nnode = end - start;

    int* s_cnt = (int*)(smem + OFF_CNT);
    const uint32_t mb = s2u(smem + OFF_MBAR);   // full(s)=mb+s*16, empty(s)=mb+s*16+8
    char* buf = smem + OFF_BUF;

    // Prologue: stage counts in smem, pass timestamps through
    for (int i = tid; i < nnode; i += NTH) {
        s_cnt[i] = counts[start + i];
        if (out_ts != nullptr) out_ts[start + i] = ts[start + i];
    }
    if (tid == 0) {
        #pragma unroll
        for (int s = 0; s < STAGES; s++) {
            mbar_init(mb + s * 16, 1);            // full: 1 expect_tx arrival
            mbar_init(mb + s * 16 + 8, NCONS_G);  // empty: owning group arrives
        }
    }
    __syncthreads();

    if (tid < CONS_BASE) {
        // ------------- producers: 2 warps, 1 active thread each -------------
        // Producer p (lane 0 of warp p) fills exactly group p's nodes
        // (i ≡ p mod 2) whose stages {p, p+2, p+4} it alone owns. Fills of
        // each stage stay strictly sequential by one thread -> parity safe.
        const int p = tid / 32;
        if ((tid & 31) == 0) {
            int s = p;   // stage of node i (cycles p, p+2, p+4)
            int j = 0;   // fill index = i / STAGES
            for (int i = p; i < nnode; i += NGROUPS) {
                int c = s_cnt[i];
                c = (c < 0) ? 0 : ((c > KK) ? KK : c);
                const uint32_t pp = (j & 1) ^ 1;          // first pass free
                mbar_wait(mb + s * 16 + 8, pp);           // wait stage empty
                const uint32_t bytes = (uint32_t)c * ROW_BYTES;
                mbar_expect_tx(mb + s * 16, bytes);
                if (bytes) {
                    const uint32_t dst =
                        s2u(buf + s * NODE_BYTES + (KK - c) * ROW_BYTES);
                    const char* src =
                        msgs + ((size_t)(start + i) * KK + (KK - c)) * ROW_BYTES;
                    bulk_copy(dst, src, bytes, mb + s * 16);
                }
                s += NGROUPS;
                if (s >= STAGES) { s -= STAGES; j++; }
            }
        }
        return;
    }

    // ---------------- consumers: 2 independent groups ----------------
    // Node i -> stage i % 6, group i % 2. 6 % 2 == 0 ⇒ every stage has a
    // fixed owning group; successive fills consumed sequentially by the same
    // threads ⇒ phase-parity protocol safe.
    const int g    = (tid - CONS_BASE) / NCONS_G;
    const int ctid = (tid - CONS_BASE) - g * NCONS_G;   // 0..191; active if < MQ

    float w1[KK * 3];
    #pragma unroll
    for (int i = 0; i < KK * 3; i++) w1[i] = __ldg(W1 + i);
    const float bb1_0 = __ldg(b1 + 0), bb1_1 = __ldg(b1 + 1), bb1_2 = __ldg(b1 + 2);
    const float w2_00 = __ldg(W2 + 0), w2_01 = __ldg(W2 + 1);
    const float w2_10 = __ldg(W2 + 2), w2_11 = __ldg(W2 + 3);
    const float w2_20 = __ldg(W2 + 4), w2_21 = __ldg(W2 + 5);
    const float bb2_0 = __ldg(b2 + 0), bb2_1 = __ldg(b2 + 1);
    const float w3_0  = __ldg(W3 + 0), w3_1  = __ldg(W3 + 1);
    const float bb3   = __ldg(b3 + 0);

    int s = g;   // stage of node i (cycles g, g+2, g+4)
    int j = 0;   // fill index = i / STAGES
    for (int i = g; i < nnode; i += NGROUPS) {
        mbar_wait(mb + s * 16, (uint32_t)(j & 1));   // wait stage full (acquire)

        if (ctid < MQ) {
            int c = s_cnt[i];
            int k0 = KK - c;
            if (k0 < 0) k0 = 0;
            if (k0 > KK) k0 = KK;

            const char* nb = buf + s * NODE_BYTES + ctid * 16;

            float h[4][3];
            #pragma unroll
            for (int l = 0; l < 4; l++) {
                h[l][0] = bb1_0; h[l][1] = bb1_1; h[l][2] = bb1_2;
            }

            #pragma unroll
            for (int k = 0; k < KK; k++) {
                if (k >= k0) {
                    const float4 v = *(const float4*)(nb + k * ROW_BYTES);
                    const float a  = w1[k * 3 + 0];
                    const float bW = w1[k * 3 + 1];
                    const float cW = w1[k * 3 + 2];
                    const float x[4] = {v.x, v.y, v.z, v.w};
                    #pragma unroll
                    for (int l = 0; l < 4; l++) {
                        h[l][0] = fmaf(x[l], a,  h[l][0]);
                        h[l][1] = fmaf(x[l], bW, h[l][1]);
                        h[l][2] = fmaf(x[l], cW, h[l][2]);
                    }
                }
            }

            float res[4];
            #pragma unroll
            for (int l = 0; l < 4; l++) {
                const float a0 = fmaxf(h[l][0], 0.0f);
                const float a1 = fmaxf(h[l][1], 0.0f);
                const float a2 = fmaxf(h[l][2], 0.0f);
                float g0 = bb2_0, g1 = bb2_1;
                g0 = fmaf(a0, w2_00, g0); g1 = fmaf(a0, w2_01, g1);
                g0 = fmaf(a1, w2_10, g0); g1 = fmaf(a1, w2_11, g1);
                g0 = fmaf(a2, w2_20, g0); g1 = fmaf(a2, w2_21, g1);
                g0 = fmaxf(g0, 0.0f);
                g1 = fmaxf(g1, 0.0f);
                res[l] = fmaf(g0, w3_0, fmaf(g1, w3_1, bb3));
            }

            float4 o;
            o.x = res[0]; o.y = res[1]; o.z = res[2]; o.w = res[3];
            out[(size_t)(start + i) * MQ + ctid] = o;
        }

        mbar_arrive(mb + s * 16 + 8);           // release stage to producer

        s += NGROUPS;
        if (s >= STAGES) { s -= STAGES; j++; }
    }
}

extern "C" void kernel_launch(void* const* d_in, const int* in_sizes, int n_in,
                              void* d_out, int out_size)
{
    const char*  msgs   = (const char*) d_in[0];
    const int*   counts = (const int*)  d_in[1];
    const float* ts     = (const float*)d_in[2];
    const float* W1     = (const float*)d_in[3];
    const float* b1     = (const float*)d_in[4];
    const float* W2     = (const float*)d_in[5];
    const float* b2     = (const float*)d_in[6];
    const float* W3     = (const float*)d_in[7];
    const float* b3     = (const float*)d_in[8];

    float* out = (float*)d_out;
    const int write_ts = (out_size >= NN * MM + NN) ? 1 : 0;
    float* out_ts = write_ts ? (out + (size_t)NN * MM) : nullptr;

    cudaFuncSetAttribute(mlp_msg_agg_pipe,
                         cudaFuncAttributeMaxDynamicSharedMemorySize, SMEM_BYTES);

    mlp_msg_agg_pipe<<<NBLK, NTH, SMEM_BYTES>>>(
        msgs, counts, ts, W1, b1, W2, b2, W3, b3,
        (float4*)out, out_ts);
}